// round 1
// baseline (speedup 1.0000x reference)
#include <cuda_runtime.h>
#include <math.h>

// ---------------- problem constants ----------------
namespace {
constexpr int B_   = 4;
constexpr int S_   = 1024;
constexpr int DIM_ = 2048;
constexpr int H_   = 16;
constexpr int QKSP_ = 192;   // NOPE(128) + ROPE(64)
constexpr int KVR_  = 512;
constexpr int M_    = B_ * S_;          // 4096 tokens
constexpr float TWO_SCALE = 0.14396396f; // 2 / sqrt(193)
}

// ---------------- scratch (device globals; no allocs allowed) ----------------
__device__ float g_q   [(size_t)M_ * H_ * QKSP_];        // (B,S,H,192)
__device__ float g_kva [(size_t)M_ * 576];               // (B,S,576)
__device__ float g_kvn [(size_t)M_ * 513];               // (B,S,513)  [t, sp]
__device__ float g_kpe [(size_t)M_ * 64];                // (B,S,64) roped
__device__ float g_kv2 [(size_t)M_ * H_ * 256];          // (B,S,H,256)
__device__ float g_qaug[(size_t)B_ * H_ * S_ * 193];     // (B,H,S,193)  [-qt, q]
__device__ float g_kaug[(size_t)B_ * H_ * S_ * 193];     // (B,H,S,193)  [+kt, k]
__device__ float g_vT  [(size_t)B_ * H_ * 129 * S_];     // (B,H,129,S)  [vt; v]^T
__device__ float g_probs[(size_t)B_ * H_ * S_ * S_];     // (B,H,S,S)
__device__ float g_avg [(size_t)B_ * H_ * S_ * 129];     // (B,H,S,129)
__device__ float g_cent[(size_t)M_ * 2064];              // (B,S,H*129)

// ---------------- reductions ----------------
__device__ __forceinline__ float block_sum_256(float v, float* sh) {
    int tid = threadIdx.x;
#pragma unroll
    for (int o = 16; o; o >>= 1) v += __shfl_xor_sync(0xffffffffu, v, o);
    __syncthreads();                      // protect sh from previous use
    if ((tid & 31) == 0) sh[tid >> 5] = v;
    __syncthreads();
    if (tid < 32) {
        float t = (tid < 8) ? sh[tid] : 0.f;
#pragma unroll
        for (int o = 4; o; o >>= 1) t += __shfl_xor_sync(0xffffffffu, t, o);
        if (tid == 0) sh[0] = t;
    }
    __syncthreads();
    return sh[0];
}

__device__ __forceinline__ float warp_sum(float v) {
#pragma unroll
    for (int o = 16; o; o >>= 1) v += __shfl_xor_sync(0xffffffffu, v, o);
    return v;
}

// ---------------- generic batched TN SGEMM ----------------
// C[m,n] = sum_k A[m,k] * W[n,k] (+ bias[n]).  A: M x K (lda), W: N x K (ldw),
// C: M x N (ldc). Batched over blockIdx.z with element strides sA/sW/sC.
// CAUSAL=true skips tiles entirely above the diagonal (M==N assumed there).
template <bool CAUSAL>
__global__ void __launch_bounds__(256)
gemm_tn_kernel(const float* __restrict__ A, int lda, long sA,
               const float* __restrict__ W, int ldw, long sW,
               float* __restrict__ C, int ldc, long sC,
               const float* __restrict__ bias,
               int M, int N, int K)
{
    constexpr int BM = 128, BN = 128, BK = 16, TM = 8, TN = 8;
    __shared__ float As[BK][BM + 4];
    __shared__ float Ws[BK][BN + 4];

    const int bm = blockIdx.y * BM;
    const int bn = blockIdx.x * BN;
    if (CAUSAL && bn > bm + BM - 1) return;

    const int z = blockIdx.z;
    A += (long)z * sA;  W += (long)z * sW;  C += (long)z * sC;

    const int tid = threadIdx.x;
    const int tx = tid & 15;         // 0..15 -> N
    const int ty = tid >> 4;         // 0..15 -> M

    float acc[TM][TN] = {};

    for (int k0 = 0; k0 < K; k0 += BK) {
#pragma unroll
        for (int i = tid; i < BM * BK; i += 256) {
            int m = i >> 4, kk = i & 15;
            int gm = bm + m, gk = k0 + kk;
            As[kk][m] = (gm < M && gk < K) ? A[(long)gm * lda + gk] : 0.f;
        }
#pragma unroll
        for (int i = tid; i < BN * BK; i += 256) {
            int n = i >> 4, kk = i & 15;
            int gn = bn + n, gk = k0 + kk;
            Ws[kk][n] = (gn < N && gk < K) ? W[(long)gn * ldw + gk] : 0.f;
        }
        __syncthreads();
#pragma unroll
        for (int kk = 0; kk < BK; ++kk) {
            float4 a0 = *(const float4*)(&As[kk][ty * TM]);
            float4 a1 = *(const float4*)(&As[kk][ty * TM + 4]);
            float4 b0 = *(const float4*)(&Ws[kk][tx * TN]);
            float4 b1 = *(const float4*)(&Ws[kk][tx * TN + 4]);
            float ar[TM] = {a0.x, a0.y, a0.z, a0.w, a1.x, a1.y, a1.z, a1.w};
            float wr[TN] = {b0.x, b0.y, b0.z, b0.w, b1.x, b1.y, b1.z, b1.w};
#pragma unroll
            for (int i = 0; i < TM; ++i)
#pragma unroll
                for (int j = 0; j < TN; ++j)
                    acc[i][j] = fmaf(ar[i], wr[j], acc[i][j]);
        }
        __syncthreads();
    }

#pragma unroll
    for (int i = 0; i < TM; ++i) {
        int gm = bm + ty * TM + i;
        if (gm >= M) continue;
#pragma unroll
        for (int j = 0; j < TN; ++j) {
            int gn = bn + tx * TN + j;
            if (gn >= N) continue;
            float v = acc[i][j];
            if (bias) v += bias[gn];
            C[(long)gm * ldc + gn] = v;
        }
    }
}

// ---------------- RMSNorm(kv) + project + k_pe RoPE ----------------
__global__ void __launch_bounds__(256)
rmsnorm_kpe_kernel(const float* __restrict__ kva, const float* __restrict__ w,
                   const float* __restrict__ fc, const float* __restrict__ fs,
                   float* __restrict__ kvn, float* __restrict__ kpe)
{
    const int tok = blockIdx.x;
    const int s = tok & (S_ - 1);
    const float* in = kva + (size_t)tok * 576;
    const int tid = threadIdx.x;
    __shared__ float sp[512];
    __shared__ float sh[8];

    float local = 0.f;
    for (int i = tid; i < 512; i += 256) { float v = in[i]; local += v * v; }
    float tot = block_sum_256(local, sh);
    float r = rsqrtf(tot * (1.0f / 512.f) + 1e-6f);

    float l2 = 0.f;
    for (int i = tid; i < 512; i += 256) {
        float v = in[i] * r * w[i];
        sp[i] = v;
        l2 += v * v;
    }
    float tot2 = block_sum_256(l2, sh);

    float* out = kvn + (size_t)tok * 513;
    if (tid == 0) out[0] = sqrtf(tot2 + 1.f);
    for (int i = tid; i < 512; i += 256) out[1 + i] = sp[i];

    if (tid < 32) {
        float x1 = in[512 + 2 * tid], x2 = in[512 + 2 * tid + 1];
        float c = fc[s * 32 + tid], sn = fs[s * 32 + tid];
        kpe[(size_t)tok * 64 + 2 * tid]     = x1 * c - x2 * sn;
        kpe[(size_t)tok * 64 + 2 * tid + 1] = x1 * sn + x2 * c;
    }
}

// ---------------- Q: RoPE + project -> (B,H,S,193) with slot0 = -qt ----------------
__global__ void __launch_bounds__(256)
post_q_kernel(const float* __restrict__ q, const float* __restrict__ fc,
              const float* __restrict__ fs, float* __restrict__ qaug)
{
    int gw = (blockIdx.x * blockDim.x + threadIdx.x) >> 5;
    int lane = threadIdx.x & 31;
    if (gw >= M_ * H_) return;
    int h = gw % H_;
    int tok = gw / H_;
    int b = tok / S_, s = tok & (S_ - 1);

    const float* qr = q + ((size_t)tok * H_ + h) * QKSP_;
    float c = fc[s * 32 + lane], sn = fs[s * 32 + lane];
    float x1 = qr[128 + 2 * lane], x2 = qr[128 + 2 * lane + 1];
    float r0 = x1 * c - x2 * sn;
    float r1 = x1 * sn + x2 * c;

    float ss = r0 * r0 + r1 * r1;
    for (int d = lane; d < 128; d += 32) { float v = qr[d]; ss += v * v; }
    ss = warp_sum(ss);

    float* out = qaug + (((size_t)b * H_ + h) * S_ + s) * 193;
    if (lane == 0) out[0] = -sqrtf(ss + 1.f);
    for (int d = lane; d < 128; d += 32) out[1 + d] = qr[d];
    out[1 + 128 + 2 * lane]     = r0;
    out[1 + 128 + 2 * lane + 1] = r1;
}

// ---------------- K/V: assemble k=[k_nope, k_pe], project; v -> vT ----------------
__global__ void __launch_bounds__(256)
post_kv_kernel(const float* __restrict__ kv2, const float* __restrict__ kpe,
               float* __restrict__ kaug, float* __restrict__ vT)
{
    int gw = (blockIdx.x * blockDim.x + threadIdx.x) >> 5;
    int lane = threadIdx.x & 31;
    if (gw >= M_ * H_) return;
    int h = gw % H_;
    int tok = gw / H_;
    int b = tok / S_, s = tok & (S_ - 1);

    const float* row = kv2 + ((size_t)tok * H_ + h) * 256;
    const float* pe  = kpe + (size_t)tok * 64;

    float ss = 0.f;
    for (int d = lane; d < 128; d += 32) { float v = row[d]; ss += v * v; }
    for (int d = lane; d < 64;  d += 32) { float v = pe[d];  ss += v * v; }
    ss = warp_sum(ss);

    float* ko = kaug + (((size_t)b * H_ + h) * S_ + s) * 193;
    if (lane == 0) ko[0] = sqrtf(ss + 1.f);
    for (int d = lane; d < 128; d += 32) ko[1 + d] = row[d];
    for (int d = lane; d < 64;  d += 32) ko[129 + d] = pe[d];

    float sv = 0.f;
    for (int d = lane; d < 128; d += 32) { float v = row[128 + d]; sv += v * v; }
    sv = warp_sum(sv);

    float* vo = vT + ((size_t)b * H_ + h) * 129 * S_;
    if (lane == 0) vo[s] = sqrtf(sv + 1.f);
    for (int d = lane; d < 128; d += 32) vo[(size_t)(1 + d) * S_ + s] = row[128 + d];
}

// ---------------- causal softmax over raw q~.k~ scores (in place) ----------------
__global__ void __launch_bounds__(256)
softmax_kernel(float* __restrict__ P)
{
    const int row = blockIdx.x;          // (b*H + h)*S + s
    const int s = row & (S_ - 1);
    float* p = P + (size_t)row * S_;
    const int tid = threadIdx.x;
    __shared__ float sh[8];

    float mx = -1e30f;
    for (int t = tid; t <= s; t += 256) mx = fmaxf(mx, p[t]);
#pragma unroll
    for (int o = 16; o; o >>= 1) mx = fmaxf(mx, __shfl_xor_sync(0xffffffffu, mx, o));
    if ((tid & 31) == 0) sh[tid >> 5] = mx;
    __syncthreads();
    if (tid < 32) {
        float v = (tid < 8) ? sh[tid] : -1e30f;
#pragma unroll
        for (int o = 4; o; o >>= 1) v = fmaxf(v, __shfl_xor_sync(0xffffffffu, v, o));
        if (tid == 0) sh[0] = v;
    }
    __syncthreads();
    mx = sh[0];
    __syncthreads();

    float sum = 0.f;
    for (int t = tid; t <= s; t += 256) {
        float e = __expf(TWO_SCALE * (p[t] - mx));
        p[t] = e;
        sum += e;
    }
    float tot = block_sum_256(sum, sh);
    float inv = 1.f / tot;
    for (int t = tid; t <= s; t += 256) p[t] *= inv;
    for (int t = s + 1 + tid; t < S_; t += 256) p[t] = 0.f;
}

// ---------------- centroid normalization -> (B,S,H*129) ----------------
__global__ void __launch_bounds__(256)
cent_kernel(const float* __restrict__ avg, float* __restrict__ cent)
{
    int gw = (blockIdx.x * blockDim.x + threadIdx.x) >> 5;
    int lane = threadIdx.x & 31;
    if (gw >= M_ * H_) return;
    int h = gw % H_;
    int tok = gw / H_;
    int b = tok / S_, s = tok & (S_ - 1);

    const float* a = avg + (((size_t)b * H_ + h) * S_ + s) * 129;
    float a0 = a[0];
    float ss = 0.f;
    for (int d = lane; d < 128; d += 32) { float v = a[1 + d]; ss += v * v; }
    ss = warp_sum(ss);
    float neg = a0 * a0 - ss;
    float denom = rsqrtf(fmaxf(fabsf(neg), 1e-8f));

    float* o = cent + (size_t)tok * 2064 + h * 129;
    if (lane == 0) o[0] = a0 * denom;
    for (int d = lane; d < 128; d += 32) o[1 + d] = a[1 + d] * denom;
}

// ---------------- final Lorentz time component of the output ----------------
__global__ void __launch_bounds__(256)
final_t_kernel(float* __restrict__ out)
{
    const int row = blockIdx.x;
    float* p = out + (size_t)row * 2048;
    const int tid = threadIdx.x;
    __shared__ float sh[8];
    float local = 0.f;
    for (int i = 1 + tid; i < 2048; i += 256) { float v = p[i]; local += v * v; }
    float tot = block_sum_256(local, sh);
    if (tid == 0) p[0] = sqrtf(tot + 1.f);
}

// ---------------- launcher ----------------
extern "C" void kernel_launch(void* const* d_in, const int* in_sizes, int n_in,
                              void* d_out, int out_size)
{
    (void)in_sizes; (void)n_in; (void)out_size;
    const float* x      = (const float*)d_in[0];
    const float* fc     = (const float*)d_in[1];
    const float* fs     = (const float*)d_in[2];
    /* d_in[3] = mask (causal; hardcoded) */
    const float* wq_w   = (const float*)d_in[4];
    const float* wq_b   = (const float*)d_in[5];
    const float* wkva_w = (const float*)d_in[6];
    const float* wkva_b = (const float*)d_in[7];
    const float* kvnw   = (const float*)d_in[8];
    const float* wkvb_w = (const float*)d_in[9];
    const float* wkvb_b = (const float*)d_in[10];
    const float* wo_w   = (const float*)d_in[11];
    const float* wo_b   = (const float*)d_in[12];
    float* out = (float*)d_out;

    float *q, *kva, *kvn, *kpe, *kv2, *qaug, *kaug, *vT, *probs, *avg, *cent;
    cudaGetSymbolAddress((void**)&q,    g_q);
    cudaGetSymbolAddress((void**)&kva,  g_kva);
    cudaGetSymbolAddress((void**)&kvn,  g_kvn);
    cudaGetSymbolAddress((void**)&kpe,  g_kpe);
    cudaGetSymbolAddress((void**)&kv2,  g_kv2);
    cudaGetSymbolAddress((void**)&qaug, g_qaug);
    cudaGetSymbolAddress((void**)&kaug, g_kaug);
    cudaGetSymbolAddress((void**)&vT,   g_vT);
    cudaGetSymbolAddress((void**)&probs,g_probs);
    cudaGetSymbolAddress((void**)&avg,  g_avg);
    cudaGetSymbolAddress((void**)&cent, g_cent);

    dim3 blk(256);

    // 1. Q projection: (4096 x 2048) @ (3072 x 2048)^T
    gemm_tn_kernel<false><<<dim3(24, 32, 1), blk>>>(
        x, DIM_, 0, wq_w, DIM_, 0, q, H_ * QKSP_, 0, wq_b, M_, H_ * QKSP_, DIM_);

    // 2. KV-A projection: (4096 x 2048) @ (576 x 2048)^T
    gemm_tn_kernel<false><<<dim3(5, 32, 1), blk>>>(
        x, DIM_, 0, wkva_w, DIM_, 0, kva, 576, 0, wkva_b, M_, 576, DIM_);

    // 3. RMSNorm + project(kv) + k_pe RoPE
    rmsnorm_kpe_kernel<<<M_, blk>>>(kva, kvnw, fc, fs, kvn, kpe);

    // 4. KV-B projection: (4096 x 513) @ (4096 x 513)^T
    gemm_tn_kernel<false><<<dim3(32, 32, 1), blk>>>(
        kvn, 513, 0, wkvb_w, 513, 0, kv2, H_ * 256, 0, wkvb_b, M_, H_ * 256, 513);

    // 5/6. build augmented q~, k~, v~^T
    post_q_kernel<<<(M_ * H_) / 8, blk>>>(q, fc, fs, qaug);
    post_kv_kernel<<<(M_ * H_) / 8, blk>>>(kv2, kpe, kaug, vT);

    // 7. batched causal scores: per (b,h)  q~(1024x193) @ k~(1024x193)^T
    gemm_tn_kernel<true><<<dim3(8, 8, B_ * H_), blk>>>(
        qaug, 193, (long)S_ * 193, kaug, 193, (long)S_ * 193,
        probs, S_, (long)S_ * S_, nullptr, S_, S_, 193);

    // 8. causal softmax
    softmax_kernel<<<B_ * H_ * S_, blk>>>(probs);

    // 9. batched PV: per (b,h)  P(1024x1024) @ vT(129x1024)^T
    gemm_tn_kernel<false><<<dim3(2, 8, B_ * H_), blk>>>(
        probs, S_, (long)S_ * S_, vT, S_, (long)129 * S_,
        avg, 129, (long)S_ * 129, nullptr, S_, 129, S_);

    // 10. centroid normalize -> (B,S,2064)
    cent_kernel<<<(M_ * H_) / 8, blk>>>(avg, cent);

    // 11. output projection -> d_out columns [1..2047]
    gemm_tn_kernel<false><<<dim3(16, 32, 1), blk>>>(
        cent, 2064, 0, wo_w, 2064, 0, out + 1, 2048, 0, wo_b, M_, 2047, 2064);

    // 12. output time component -> column 0
    final_t_kernel<<<M_, blk>>>(out);
}